// round 5
// baseline (speedup 1.0000x reference)
#include <cuda_runtime.h>
#include <cuda_bf16.h>

#define NN 100000
#define NE 3200000

typedef unsigned long long ull;

// ---------------- scratch (static device arrays; no allocs) ----------------
__device__ int   g_is64;
__device__ int   g_hist[NN];
__device__ int   g_rowptr[NN + 1];
__device__ int   g_cursor[NN];
__device__ int   g_col[NE];
__device__ int   g_part[256];
__device__ float g_dinv[NN];
__device__ float g_h0s[NN * 16];   // dinv-scaled x@W1
__device__ float g_x1 [NN * 16];   // relu layer-1 output (raw)
__device__ float g_h1s[NN * 16];   // dinv-scaled x1@W2
__device__ float g_x2 [NN * 16];   // relu layer-2 output (raw)
__device__ float g_hs [NN * 16];   // dinv-scaled JK output

// ---------------- helpers ----------------
__device__ __forceinline__ float tanha(float x) {
    float y;
    asm("tanh.approx.f32 %0, %1;" : "=f"(y) : "f"(x));
    return y;
}
__device__ __forceinline__ float sigf(float x) {
    return fmaf(0.5f, tanha(0.5f * x), 0.5f);
}
__device__ __forceinline__ ull fma2(ull a, ull b, ull c) {
    ull d;
    asm("fma.rn.f32x2 %0, %1, %2, %3;" : "=l"(d) : "l"(a), "l"(b), "l"(c));
    return d;
}
__device__ __forceinline__ ull pack2(float a, float b) {
    ull r;
    asm("mov.b64 %0, {%1, %2};" : "=l"(r) : "f"(a), "f"(b));
    return r;
}
__device__ __forceinline__ float2 unpack2(ull v) {
    float2 r;
    asm("mov.b64 {%0, %1}, %2;" : "=f"(r.x), "=f"(r.y) : "l"(v));
    return r;
}

// ---------------- 1) hist zero + edge dtype detection (fused) ----------------
// Node ids < 1e5, so int64 storage -> every odd 32-bit word is 0.
// If int32, odd words are random node indices (P(all 8192 sampled zero) ~ 0).
__global__ void k_init(const unsigned* __restrict__ e) {
    int i = blockIdx.x * 256 + threadIdx.x;
    if (i < NN) g_hist[i] = 0;
    if (blockIdx.x == 0) {
        __shared__ int found;
        if (threadIdx.x == 0) found = 0;
        __syncthreads();
        int f = 0;
        for (int k = threadIdx.x; k < 8192; k += 256)
            f |= (e[2 * k + 1] != 0u);
        if (f) atomicOr(&found, 1);
        __syncthreads();
        if (threadIdx.x == 0) g_is64 = found ? 0 : 1;
    }
}

// ---------------- 2) degree histogram (reads dst half only) ----------------
__global__ void k_deg(const void* __restrict__ edges) {
    int e = blockIdx.x * 256 + threadIdx.x;
    int d;
    if (g_is64) {
        d = (int)((const long long*)edges)[e + NE];
    } else {
        d = ((const int*)edges)[e + NE];
    }
    atomicAdd(&g_hist[d], 1);
}

// ---------------- 3) scan hist -> rowptr, dinv ----------------
__global__ void k_part() {
    __shared__ int sh[512];
    int t = threadIdx.x;
    int i = blockIdx.x * 512 + t;
    int v = (i < NN) ? g_hist[i] : 0;
    if (i < NN) g_dinv[i] = rsqrtf((float)v + 1.0f);
    sh[t] = v;
    __syncthreads();
    for (int off = 256; off > 0; off >>= 1) {
        if (t < off) sh[t] += sh[t + off];
        __syncthreads();
    }
    if (t == 0) g_part[blockIdx.x] = sh[0];
}

__global__ void k_scanpart() {
    __shared__ int sh[256];
    int t = threadIdx.x;
    int v = (t < 196) ? g_part[t] : 0;
    sh[t] = v;
    __syncthreads();
    for (int off = 1; off < 256; off <<= 1) {
        int add = (t >= off) ? sh[t - off] : 0;
        __syncthreads();
        sh[t] += add;
        __syncthreads();
    }
    if (t < 196) g_part[t] = sh[t] - v;   // exclusive
    if (t == 0) g_rowptr[NN] = NE;
}

__global__ void k_rowptr() {
    __shared__ int sh[512];
    int t = threadIdx.x;
    int i = blockIdx.x * 512 + t;
    int v = (i < NN) ? g_hist[i] : 0;
    sh[t] = v;
    __syncthreads();
    for (int off = 1; off < 512; off <<= 1) {
        int add = (t >= off) ? sh[t - off] : 0;
        __syncthreads();
        sh[t] += add;
        __syncthreads();
    }
    int excl = sh[t] - v + g_part[blockIdx.x];
    if (i < NN) {
        g_rowptr[i] = excl;
        g_cursor[i] = excl;
    }
}

// ---------------- 4) scatter edges into CSR (reads edges directly) ----------
__global__ void k_scatter(const void* __restrict__ edges) {
    int e = blockIdx.x * 256 + threadIdx.x;
    int s, d;
    if (g_is64) {
        const long long* p = (const long long*)edges;
        s = (int)p[e];
        d = (int)p[e + NE];
    } else {
        const int* p = (const int*)edges;
        s = p[e];
        d = p[e + NE];
    }
    int pos = atomicAdd(&g_cursor[d], 1);
    g_col[pos] = s;
}

// ---------------- 5) h0s = dinv[v] * (x @ W1) ----------------
__global__ void __launch_bounds__(256) k_xw1(const float* __restrict__ x,
                                             const float* __restrict__ W1) {
    __shared__ __align__(16) float Wsh[512 * 16];   // 32 KB
    __shared__ __align__(16) float xsh[64 * 36];    // 64 rows x 32 k, padded
    int t = threadIdx.x;
    for (int i = t; i < 8192; i += 256) Wsh[i] = W1[i];
    int row0 = blockIdx.x * 64;
    int jq = t & 3;
    int r  = t >> 2;
    ull acc01 = 0ULL, acc23 = 0ULL;
    for (int kt = 0; kt < 512; kt += 32) {
        __syncthreads();
        for (int idx = t; idx < 512; idx += 256) {
            int rr = idx >> 3, kq = idx & 7;
            int grow = row0 + rr;
            float4 v = (grow < NN) ? *(const float4*)&x[grow * 512 + kt + kq * 4]
                                   : make_float4(0.f, 0.f, 0.f, 0.f);
            *(float4*)&xsh[rr * 36 + kq * 4] = v;
        }
        __syncthreads();
        #pragma unroll
        for (int k = 0; k < 32; k += 4) {
            float4 xv = *(float4*)&xsh[r * 36 + k];
            ulonglong2 w;
            ull p;
            w = *(ulonglong2*)&Wsh[(kt + k + 0) * 16 + jq * 4];
            p = pack2(xv.x, xv.x);
            acc01 = fma2(w.x, p, acc01); acc23 = fma2(w.y, p, acc23);
            w = *(ulonglong2*)&Wsh[(kt + k + 1) * 16 + jq * 4];
            p = pack2(xv.y, xv.y);
            acc01 = fma2(w.x, p, acc01); acc23 = fma2(w.y, p, acc23);
            w = *(ulonglong2*)&Wsh[(kt + k + 2) * 16 + jq * 4];
            p = pack2(xv.z, xv.z);
            acc01 = fma2(w.x, p, acc01); acc23 = fma2(w.y, p, acc23);
            w = *(ulonglong2*)&Wsh[(kt + k + 3) * 16 + jq * 4];
            p = pack2(xv.w, xv.w);
            acc01 = fma2(w.x, p, acc01); acc23 = fma2(w.y, p, acc23);
        }
    }
    int row = row0 + r;
    if (row < NN) {
        float dv = g_dinv[row];
        float2 a01 = unpack2(acc01), a23 = unpack2(acc23);
        float4 res;
        res.x = dv * a01.x; res.y = dv * a01.y;
        res.z = dv * a23.x; res.w = dv * a23.y;
        *(float4*)&g_h0s[row * 16 + jq * 4] = res;
    }
}

// ---------------- gather core with cooperative index loading ----------------
// 16 lanes per node; lane j loads g_col[i+j] (coalesced), broadcast via shfl.
// mask covers only this node's 16 lanes (they share the loop trip count).
__device__ __forceinline__ float gather_sum(int v, int j, unsigned gb,
                                            const float* __restrict__ in) {
    unsigned mask = 0xFFFFu << gb;
    int b = g_rowptr[v], e = g_rowptr[v + 1];
    float acc = in[v * 16 + j];          // self-loop term (already dinv-scaled)
    int i = b;
    int idx = (b + j < e) ? g_col[b + j] : 0;
    for (; i + 16 <= e; i += 16) {
        int cur = idx;
        int nx = i + 16;
        idx = (nx + j < e) ? g_col[nx + j] : 0;   // prefetch next chunk
        #pragma unroll
        for (int k = 0; k < 16; k++) {
            int s = __shfl_sync(mask, cur, gb + k);
            acc += in[s * 16 + j];
        }
    }
    int n = e - i;
    for (int k = 0; k < n; k++) {
        int s = __shfl_sync(mask, idx, gb + k);
        acc += in[s * 16 + j];
    }
    return g_dinv[v] * acc;
}

// ---------------- 6) agg1 + bias + relu, fused x1@W2 ----------------
__global__ void k_agg1(const float* __restrict__ b1, const float* __restrict__ W2) {
    __shared__ float W2s[256];
    int tid = threadIdx.x;
    W2s[tid] = W2[tid];
    __syncthreads();
    int v = blockIdx.x * 16 + (tid >> 4);
    int j = tid & 15;
    unsigned gb = (tid & 31) & 16;
    float val = gather_sum(v, j, gb, g_h0s);
    float x1v = fmaxf(val + b1[j], 0.f);
    g_x1[v * 16 + j] = x1v;
    float h1 = 0.f;
    #pragma unroll
    for (int k = 0; k < 16; k++) {
        float xk = __shfl_sync(0xffffffffu, x1v, gb + k);
        h1 = fmaf(xk, W2s[k * 16 + j], h1);
    }
    g_h1s[v * 16 + j] = g_dinv[v] * h1;
}

// ---------------- 7) agg2 + bias + relu ----------------
__global__ void k_agg2(const float* __restrict__ b2) {
    int tid = threadIdx.x;
    int v = blockIdx.x * 16 + (tid >> 4);
    int j = tid & 15;
    unsigned gb = (tid & 31) & 16;
    float val = gather_sum(v, j, gb, g_h1s);
    g_x2[v * 16 + j] = fmaxf(val + b2[j], 0.f);
}

// ---------------- 8) JK bidirectional LSTM + attention ----------------
// Shared weight layout (transposed, j-contiguous per k):
//   [0:2048)      F w_ih^T     ws[k*128 + j] = w_ih[j][k]
//   [2048:6144)   F w_hh^T
//   [6144:8192)   B w_ih^T
//   [8192:12288)  B w_hh^T     -> exactly 48 KB
__device__ __forceinline__ void lstm_cell(
    const float* __restrict__ wih_t, const float* __restrict__ whh_t,
    const float* __restrict__ bias,
    const ull* __restrict__ xp, const ull* __restrict__ hp,
    float* __restrict__ c, float* __restrict__ hn)
{
    #pragma unroll 1
    for (int j = 0; j < 32; j += 4) {
        ull a0, a1, a2, a3, a4, a5, a6, a7;
        {
            ulonglong2 b0 = *(const ulonglong2*)(bias + 0  + j);
            ulonglong2 b1 = *(const ulonglong2*)(bias + 32 + j);
            ulonglong2 b2 = *(const ulonglong2*)(bias + 64 + j);
            ulonglong2 b3 = *(const ulonglong2*)(bias + 96 + j);
            a0 = b0.x; a1 = b0.y; a2 = b1.x; a3 = b1.y;
            a4 = b2.x; a5 = b2.y; a6 = b3.x; a7 = b3.y;
        }
        #pragma unroll
        for (int k = 0; k < 16; k++) {
            ull p = xp[k];
            const float* w = wih_t + k * 128 + j;
            ulonglong2 w0 = *(const ulonglong2*)(w);
            ulonglong2 w1 = *(const ulonglong2*)(w + 32);
            ulonglong2 w2 = *(const ulonglong2*)(w + 64);
            ulonglong2 w3 = *(const ulonglong2*)(w + 96);
            a0 = fma2(w0.x, p, a0); a1 = fma2(w0.y, p, a1);
            a2 = fma2(w1.x, p, a2); a3 = fma2(w1.y, p, a3);
            a4 = fma2(w2.x, p, a4); a5 = fma2(w2.y, p, a5);
            a6 = fma2(w3.x, p, a6); a7 = fma2(w3.y, p, a7);
        }
        #pragma unroll
        for (int k = 0; k < 32; k++) {
            ull p = hp[k];
            const float* w = whh_t + k * 128 + j;
            ulonglong2 w0 = *(const ulonglong2*)(w);
            ulonglong2 w1 = *(const ulonglong2*)(w + 32);
            ulonglong2 w2 = *(const ulonglong2*)(w + 64);
            ulonglong2 w3 = *(const ulonglong2*)(w + 96);
            a0 = fma2(w0.x, p, a0); a1 = fma2(w0.y, p, a1);
            a2 = fma2(w1.x, p, a2); a3 = fma2(w1.y, p, a3);
            a4 = fma2(w2.x, p, a4); a5 = fma2(w2.y, p, a5);
            a6 = fma2(w3.x, p, a6); a7 = fma2(w3.y, p, a7);
        }
        float2 i01 = unpack2(a0), i23 = unpack2(a1);
        float2 f01 = unpack2(a2), f23 = unpack2(a3);
        float2 g01 = unpack2(a4), g23 = unpack2(a5);
        float2 o01 = unpack2(a6), o23 = unpack2(a7);
        float iv[4] = {i01.x, i01.y, i23.x, i23.y};
        float fv[4] = {f01.x, f01.y, f23.x, f23.y};
        float gv[4] = {g01.x, g01.y, g23.x, g23.y};
        float ov[4] = {o01.x, o01.y, o23.x, o23.y};
        #pragma unroll
        for (int q = 0; q < 4; q++) {
            float cc = sigf(fv[q]) * c[j + q] + sigf(iv[q]) * tanha(gv[q]);
            c[j + q] = cc;
            hn[j + q] = sigf(ov[q]) * tanha(cc);
        }
    }
}

__global__ void __launch_bounds__(128)
k_lstm(const float* __restrict__ wihF, const float* __restrict__ whhF,
       const float* __restrict__ bF,
       const float* __restrict__ wihB, const float* __restrict__ whhB,
       const float* __restrict__ bB,
       const float* __restrict__ attw)
{
    __shared__ __align__(16) float ws[12288];   // exactly 48 KB
    int tid = threadIdx.x;
    for (int i = tid; i < 2048; i += 128) {
        int jj = i >> 4, kk = i & 15;
        ws[kk * 128 + jj]        = wihF[i];
        ws[6144 + kk * 128 + jj] = wihB[i];
    }
    for (int i = tid; i < 4096; i += 128) {
        int jj = i >> 5, kk = i & 31;
        ws[2048 + kk * 128 + jj] = whhF[i];
        ws[8192 + kk * 128 + jj] = whhB[i];
    }
    __syncthreads();
    int v = blockIdx.x * 128 + tid;
    if (v >= NN) return;

    const float* x1g = g_x1 + v * 16;
    const float* x2g = g_x2 + v * 16;
    ull xp[16], hp[32];
    float c[32], hn[32];
    float s0 = 0.f, s1 = 0.f;

    #pragma unroll
    for (int q = 0; q < 4; q++) {
        float4 t = *(const float4*)(x1g + 4 * q);
        xp[4 * q + 0] = pack2(t.x, t.x); xp[4 * q + 1] = pack2(t.y, t.y);
        xp[4 * q + 2] = pack2(t.z, t.z); xp[4 * q + 3] = pack2(t.w, t.w);
    }
    #pragma unroll
    for (int k = 0; k < 32; k++) { hp[k] = 0ULL; c[k] = 0.f; }

    lstm_cell(ws, ws + 2048, bF, xp, hp, c, hn);          // hf0
    #pragma unroll
    for (int k = 0; k < 32; k++) { s0 += hn[k] * attw[k]; hp[k] = pack2(hn[k], hn[k]); }

    #pragma unroll
    for (int q = 0; q < 4; q++) {
        float4 t = *(const float4*)(x2g + 4 * q);
        xp[4 * q + 0] = pack2(t.x, t.x); xp[4 * q + 1] = pack2(t.y, t.y);
        xp[4 * q + 2] = pack2(t.z, t.z); xp[4 * q + 3] = pack2(t.w, t.w);
    }
    lstm_cell(ws, ws + 2048, bF, xp, hp, c, hn);          // hf1
    #pragma unroll
    for (int k = 0; k < 32; k++) s1 += hn[k] * attw[k];

    #pragma unroll
    for (int k = 0; k < 32; k++) { hp[k] = 0ULL; c[k] = 0.f; }
    lstm_cell(ws + 6144, ws + 8192, bB, xp, hp, c, hn);   // hb1 (input x2)
    #pragma unroll
    for (int k = 0; k < 32; k++) { s1 += hn[k] * attw[32 + k]; hp[k] = pack2(hn[k], hn[k]); }

    #pragma unroll
    for (int q = 0; q < 4; q++) {
        float4 t = *(const float4*)(x1g + 4 * q);
        xp[4 * q + 0] = pack2(t.x, t.x); xp[4 * q + 1] = pack2(t.y, t.y);
        xp[4 * q + 2] = pack2(t.z, t.z); xp[4 * q + 3] = pack2(t.w, t.w);
    }
    lstm_cell(ws + 6144, ws + 8192, bB, xp, hp, c, hn);   // hb0
    #pragma unroll
    for (int k = 0; k < 32; k++) s0 += hn[k] * attw[32 + k];

    // softmax over the 2 scores (att_b cancels)
    float m = fmaxf(s0, s1);
    float e0 = __expf(s0 - m), e1 = __expf(s1 - m);
    float inv = __fdividef(1.f, e0 + e1);
    float a0 = e0 * inv, a1 = e1 * inv;
    float dv = g_dinv[v];
    float* o = g_hs + v * 16;
    #pragma unroll
    for (int q = 0; q < 4; q++) {
        float4 t1 = *(const float4*)(x1g + 4 * q);
        float4 t2 = *(const float4*)(x2g + 4 * q);
        float4 r;
        r.x = dv * (a0 * t1.x + a1 * t2.x);
        r.y = dv * (a0 * t1.y + a1 * t2.y);
        r.z = dv * (a0 * t1.z + a1 * t2.z);
        r.w = dv * (a0 * t1.w + a1 * t2.w);
        *(float4*)(o + 4 * q) = r;
    }
}

// ---------------- 9) APPNP agg + linear + log_softmax ----------------
__global__ void k_out(const float* __restrict__ linw, const float* __restrict__ linb,
                      float* __restrict__ out)
{
    __shared__ float LW[640];
    __shared__ float LB[40];
    int tid = threadIdx.x;
    for (int i = tid; i < 640; i += 256) LW[i] = linw[i];
    if (tid < 40) LB[tid] = linb[tid];
    __syncthreads();

    int v = blockIdx.x * 16 + (tid >> 4);
    int j = tid & 15;
    unsigned gb = (tid & 31) & 16;   // lane base of this node's 16-group
    float hval = gather_sum(v, j, gb, g_hs);

    float l0 = LB[j];
    float l1 = LB[j + 16];
    float l2 = (j < 8) ? LB[j + 32] : -1e30f;
    #pragma unroll
    for (int k = 0; k < 16; k++) {
        float hk = __shfl_sync(0xffffffffu, hval, gb + k);
        l0 = fmaf(hk, LW[k * 40 + j], l0);
        l1 = fmaf(hk, LW[k * 40 + j + 16], l1);
        if (j < 8) l2 = fmaf(hk, LW[k * 40 + j + 32], l2);
    }
    // group max over the 40 logits
    float m = fmaxf(l0, l1);
    if (j < 8) m = fmaxf(m, l2);
    #pragma unroll
    for (int off = 8; off > 0; off >>= 1)
        m = fmaxf(m, __shfl_xor_sync(0xffffffffu, m, off));
    float ssum = __expf(l0 - m) + __expf(l1 - m) + ((j < 8) ? __expf(l2 - m) : 0.f);
    #pragma unroll
    for (int off = 8; off > 0; off >>= 1)
        ssum += __shfl_xor_sync(0xffffffffu, ssum, off);
    float lse = m + __logf(ssum);

    out[v * 40 + j]      = l0 - lse;
    out[v * 40 + j + 16] = l1 - lse;
    if (j < 8) out[v * 40 + j + 32] = l2 - lse;
}

// ---------------- launch ----------------
extern "C" void kernel_launch(void* const* d_in, const int* in_sizes, int n_in,
                              void* d_out, int out_size) {
    const float* x     = (const float*)d_in[0];
    const void*  edges = d_in[1];
    const float* W1    = (const float*)d_in[2];
    const float* b1    = (const float*)d_in[3];
    const float* W2    = (const float*)d_in[4];
    const float* b2    = (const float*)d_in[5];
    const float* wihF  = (const float*)d_in[6];
    const float* whhF  = (const float*)d_in[7];
    const float* bF    = (const float*)d_in[8];
    const float* wihB  = (const float*)d_in[9];
    const float* whhB  = (const float*)d_in[10];
    const float* bB    = (const float*)d_in[11];
    const float* attw  = (const float*)d_in[12];
    const float* linw  = (const float*)d_in[14];
    const float* linb  = (const float*)d_in[15];
    float* out = (float*)d_out;

    k_init<<<(NN + 255) / 256, 256>>>((const unsigned*)edges);
    k_deg<<<NE / 256, 256>>>(edges);
    k_part<<<196, 512>>>();
    k_scanpart<<<1, 256>>>();
    k_rowptr<<<196, 512>>>();
    k_scatter<<<NE / 256, 256>>>(edges);
    k_xw1<<<(NN + 63) / 64, 256>>>(x, W1);
    k_agg1<<<NN / 16, 256>>>(b1, W2);
    k_agg2<<<NN / 16, 256>>>(b2);
    k_lstm<<<(NN + 127) / 128, 128>>>(wihF, whhF, bF, wihB, whhB, bB, attw);
    k_out<<<NN / 16, 256>>>(linw, linb, out);
}

// round 6
// speedup vs baseline: 1.2329x; 1.2329x over previous
#include <cuda_runtime.h>
#include <cuda_bf16.h>

#define NN 100000
#define NE 3200000

typedef unsigned long long ull;

// ---------------- scratch (static device arrays; no allocs) ----------------
__device__ int   g_is64;
__device__ int   g_hist[NN];
__device__ int   g_rowptr[NN + 1];
__device__ int   g_cursor[NN];
__device__ int   g_col[NE];
__device__ int   g_part[256];
__device__ float g_dinv[NN];
__device__ float g_h0s[NN * 16];   // dinv-scaled x@W1
__device__ float g_x1 [NN * 16];   // relu layer-1 output (raw)
__device__ float g_h1s[NN * 16];   // dinv-scaled x1@W2
__device__ float g_x2 [NN * 16];   // relu layer-2 output (raw)
__device__ float g_hs [NN * 16];   // dinv-scaled JK output

// ---------------- helpers ----------------
__device__ __forceinline__ float tanha(float x) {
    float y;
    asm("tanh.approx.f32 %0, %1;" : "=f"(y) : "f"(x));
    return y;
}
__device__ __forceinline__ float sigf(float x) {
    return fmaf(0.5f, tanha(0.5f * x), 0.5f);
}
__device__ __forceinline__ ull fma2(ull a, ull b, ull c) {
    ull d;
    asm("fma.rn.f32x2 %0, %1, %2, %3;" : "=l"(d) : "l"(a), "l"(b), "l"(c));
    return d;
}
__device__ __forceinline__ ull pack2(float a, float b) {
    ull r;
    asm("mov.b64 %0, {%1, %2};" : "=l"(r) : "f"(a), "f"(b));
    return r;
}
__device__ __forceinline__ float2 unpack2(ull v) {
    float2 r;
    asm("mov.b64 {%0, %1}, %2;" : "=f"(r.x), "=f"(r.y) : "l"(v));
    return r;
}

// ---------------- 1) hist zero + edge dtype detection (fused) ----------------
__global__ void k_init(const unsigned* __restrict__ e) {
    int i = blockIdx.x * 256 + threadIdx.x;
    if (i < NN) g_hist[i] = 0;
    if (blockIdx.x == 0) {
        __shared__ int found;
        if (threadIdx.x == 0) found = 0;
        __syncthreads();
        int f = 0;
        for (int k = threadIdx.x; k < 8192; k += 256)
            f |= (e[2 * k + 1] != 0u);
        if (f) atomicOr(&found, 1);
        __syncthreads();
        if (threadIdx.x == 0) g_is64 = found ? 0 : 1;
    }
}

// ---------------- 2) degree histogram (reads dst half only) ----------------
__global__ void k_deg(const void* __restrict__ edges) {
    int e = blockIdx.x * 256 + threadIdx.x;
    int d;
    if (g_is64) {
        d = (int)((const long long*)edges)[e + NE];
    } else {
        d = ((const int*)edges)[e + NE];
    }
    atomicAdd(&g_hist[d], 1);
}

// ---------------- 3) scan hist -> rowptr, dinv ----------------
__global__ void k_part() {
    __shared__ int sh[512];
    int t = threadIdx.x;
    int i = blockIdx.x * 512 + t;
    int v = (i < NN) ? g_hist[i] : 0;
    if (i < NN) g_dinv[i] = rsqrtf((float)v + 1.0f);
    sh[t] = v;
    __syncthreads();
    for (int off = 256; off > 0; off >>= 1) {
        if (t < off) sh[t] += sh[t + off];
        __syncthreads();
    }
    if (t == 0) g_part[blockIdx.x] = sh[0];
}

__global__ void k_scanpart() {
    __shared__ int sh[256];
    int t = threadIdx.x;
    int v = (t < 196) ? g_part[t] : 0;
    sh[t] = v;
    __syncthreads();
    for (int off = 1; off < 256; off <<= 1) {
        int add = (t >= off) ? sh[t - off] : 0;
        __syncthreads();
        sh[t] += add;
        __syncthreads();
    }
    if (t < 196) g_part[t] = sh[t] - v;   // exclusive
    if (t == 0) g_rowptr[NN] = NE;
}

__global__ void k_rowptr() {
    __shared__ int sh[512];
    int t = threadIdx.x;
    int i = blockIdx.x * 512 + t;
    int v = (i < NN) ? g_hist[i] : 0;
    sh[t] = v;
    __syncthreads();
    for (int off = 1; off < 512; off <<= 1) {
        int add = (t >= off) ? sh[t - off] : 0;
        __syncthreads();
        sh[t] += add;
        __syncthreads();
    }
    int excl = sh[t] - v + g_part[blockIdx.x];
    if (i < NN) {
        g_rowptr[i] = excl;
        g_cursor[i] = excl;
    }
}

// ---------------- 4) scatter edges into CSR (reads edges directly) ----------
__global__ void k_scatter(const void* __restrict__ edges) {
    int e = blockIdx.x * 256 + threadIdx.x;
    int s, d;
    if (g_is64) {
        const long long* p = (const long long*)edges;
        s = (int)p[e];
        d = (int)p[e + NE];
    } else {
        const int* p = (const int*)edges;
        s = p[e];
        d = p[e + NE];
    }
    int pos = atomicAdd(&g_cursor[d], 1);
    g_col[pos] = s;
}

// ---------------- 5) h0s = dinv[v] * (x @ W1) ----------------
__global__ void __launch_bounds__(256) k_xw1(const float* __restrict__ x,
                                             const float* __restrict__ W1) {
    __shared__ __align__(16) float Wsh[512 * 16];   // 32 KB
    __shared__ __align__(16) float xsh[64 * 36];    // 64 rows x 32 k, padded
    int t = threadIdx.x;
    for (int i = t; i < 8192; i += 256) Wsh[i] = W1[i];
    int row0 = blockIdx.x * 64;
    int jq = t & 3;
    int r  = t >> 2;
    ull acc01 = 0ULL, acc23 = 0ULL;
    for (int kt = 0; kt < 512; kt += 32) {
        __syncthreads();
        for (int idx = t; idx < 512; idx += 256) {
            int rr = idx >> 3, kq = idx & 7;
            int grow = row0 + rr;
            float4 v = (grow < NN) ? *(const float4*)&x[grow * 512 + kt + kq * 4]
                                   : make_float4(0.f, 0.f, 0.f, 0.f);
            *(float4*)&xsh[rr * 36 + kq * 4] = v;
        }
        __syncthreads();
        #pragma unroll
        for (int k = 0; k < 32; k += 4) {
            float4 xv = *(float4*)&xsh[r * 36 + k];
            ulonglong2 w;
            ull p;
            w = *(ulonglong2*)&Wsh[(kt + k + 0) * 16 + jq * 4];
            p = pack2(xv.x, xv.x);
            acc01 = fma2(w.x, p, acc01); acc23 = fma2(w.y, p, acc23);
            w = *(ulonglong2*)&Wsh[(kt + k + 1) * 16 + jq * 4];
            p = pack2(xv.y, xv.y);
            acc01 = fma2(w.x, p, acc01); acc23 = fma2(w.y, p, acc23);
            w = *(ulonglong2*)&Wsh[(kt + k + 2) * 16 + jq * 4];
            p = pack2(xv.z, xv.z);
            acc01 = fma2(w.x, p, acc01); acc23 = fma2(w.y, p, acc23);
            w = *(ulonglong2*)&Wsh[(kt + k + 3) * 16 + jq * 4];
            p = pack2(xv.w, xv.w);
            acc01 = fma2(w.x, p, acc01); acc23 = fma2(w.y, p, acc23);
        }
    }
    int row = row0 + r;
    if (row < NN) {
        float dv = g_dinv[row];
        float2 a01 = unpack2(acc01), a23 = unpack2(acc23);
        float4 res;
        res.x = dv * a01.x; res.y = dv * a01.y;
        res.z = dv * a23.x; res.w = dv * a23.y;
        *(float4*)&g_h0s[row * 16 + jq * 4] = res;
    }
}

// ---------------- gather core (simple; same-address idx loads broadcast) ----
__device__ __forceinline__ float gather_sum(int v, int j, const float* __restrict__ in) {
    int b = g_rowptr[v], e = g_rowptr[v + 1];
    float acc = in[v * 16 + j];          // self-loop term (already dinv-scaled)
    int i = b;
    for (; i + 8 <= e; i += 8) {
        int s0 = g_col[i],     s1 = g_col[i + 1], s2 = g_col[i + 2], s3 = g_col[i + 3];
        int s4 = g_col[i + 4], s5 = g_col[i + 5], s6 = g_col[i + 6], s7 = g_col[i + 7];
        float v0 = in[s0 * 16 + j], v1 = in[s1 * 16 + j];
        float v2 = in[s2 * 16 + j], v3 = in[s3 * 16 + j];
        float v4 = in[s4 * 16 + j], v5 = in[s5 * 16 + j];
        float v6 = in[s6 * 16 + j], v7 = in[s7 * 16 + j];
        acc += ((v0 + v1) + (v2 + v3)) + ((v4 + v5) + (v6 + v7));
    }
    for (; i < e; i++) acc += in[g_col[i] * 16 + j];
    return g_dinv[v] * acc;
}

// ---------------- 6) agg1 + bias + relu, fused x1@W2 ----------------
__global__ void k_agg1(const float* __restrict__ b1, const float* __restrict__ W2) {
    __shared__ float W2s[256];
    int tid = threadIdx.x;
    W2s[tid] = W2[tid];
    __syncthreads();
    int v = blockIdx.x * 16 + (tid >> 4);
    int j = tid & 15;
    float val = gather_sum(v, j, g_h0s);
    float x1v = fmaxf(val + b1[j], 0.f);
    g_x1[v * 16 + j] = x1v;
    unsigned gb = (tid & 31) & 16;
    float h1 = 0.f;
    #pragma unroll
    for (int k = 0; k < 16; k++) {
        float xk = __shfl_sync(0xffffffffu, x1v, gb + k);
        h1 = fmaf(xk, W2s[k * 16 + j], h1);
    }
    g_h1s[v * 16 + j] = g_dinv[v] * h1;
}

// ---------------- 7) agg2 + bias + relu ----------------
__global__ void k_agg2(const float* __restrict__ b2) {
    int tid = threadIdx.x;
    int v = blockIdx.x * 16 + (tid >> 4);
    int j = tid & 15;
    float val = gather_sum(v, j, g_h1s);
    g_x2[v * 16 + j] = fmaxf(val + b2[j], 0.f);
}

// ---------------- 8) JK bidirectional LSTM + attention ----------------
// Shared weight layout (transposed, j-contiguous per k):
//   [0:2048)      F w_ih^T     ws[k*128 + j] = w_ih[j][k]
//   [2048:6144)   F w_hh^T
//   [6144:8192)   B w_ih^T
//   [8192:12288)  B w_hh^T     -> exactly 48 KB
//
// Cell 1 of each direction has h=c=0: skip the whole w_hh GEMM and the f*c
// term. hf1/hb0 are consumed only by the attention dot product: accumulate
// inline per j-chunk, never stored. Broadcast operand pairs packed on the fly
// -> persistent state is 96 floats, no spills.

// first cell: h=0, c=0. writes h[], cv[]; accumulates s += h . attw
__device__ __forceinline__ void cell_first(
    const float* __restrict__ wih_t, const float* __restrict__ bias,
    const float* __restrict__ xv, float* __restrict__ h, float* __restrict__ cv,
    const float* __restrict__ attw, float& s)
{
    #pragma unroll 1
    for (int j = 0; j < 32; j += 4) {
        ull a0, a1, a2, a3, a4, a5, a6, a7;
        {
            ulonglong2 b0 = *(const ulonglong2*)(bias + 0  + j);
            ulonglong2 b1 = *(const ulonglong2*)(bias + 32 + j);
            ulonglong2 b2 = *(const ulonglong2*)(bias + 64 + j);
            ulonglong2 b3 = *(const ulonglong2*)(bias + 96 + j);
            a0 = b0.x; a1 = b0.y; a2 = b1.x; a3 = b1.y;
            a4 = b2.x; a5 = b2.y; a6 = b3.x; a7 = b3.y;
        }
        #pragma unroll
        for (int k = 0; k < 16; k++) {
            ull p = pack2(xv[k], xv[k]);
            const float* w = wih_t + k * 128 + j;
            ulonglong2 w0 = *(const ulonglong2*)(w);
            ulonglong2 w1 = *(const ulonglong2*)(w + 32);
            ulonglong2 w2 = *(const ulonglong2*)(w + 64);
            ulonglong2 w3 = *(const ulonglong2*)(w + 96);
            a0 = fma2(w0.x, p, a0); a1 = fma2(w0.y, p, a1);
            a2 = fma2(w1.x, p, a2); a3 = fma2(w1.y, p, a3);
            a4 = fma2(w2.x, p, a4); a5 = fma2(w2.y, p, a5);
            a6 = fma2(w3.x, p, a6); a7 = fma2(w3.y, p, a7);
        }
        float2 i01 = unpack2(a0), i23 = unpack2(a1);
        float2 g01 = unpack2(a4), g23 = unpack2(a5);
        float2 o01 = unpack2(a6), o23 = unpack2(a7);
        float iv[4] = {i01.x, i01.y, i23.x, i23.y};
        float gv[4] = {g01.x, g01.y, g23.x, g23.y};
        float ov[4] = {o01.x, o01.y, o23.x, o23.y};
        #pragma unroll
        for (int q = 0; q < 4; q++) {
            float cc = sigf(iv[q]) * tanha(gv[q]);     // f-gate * 0 dropped
            cv[j + q] = cc;
            float hv = sigf(ov[q]) * tanha(cc);
            h[j + q] = hv;
            s += hv * __ldg(&attw[j + q]);
        }
    }
}

// second cell: uses h[], cv[]; output only feeds attention sum (discarded).
__device__ __forceinline__ void cell_second(
    const float* __restrict__ wih_t, const float* __restrict__ whh_t,
    const float* __restrict__ bias,
    const float* __restrict__ xv, const float* __restrict__ h,
    const float* __restrict__ cv,
    const float* __restrict__ attw, float& s)
{
    #pragma unroll 1
    for (int j = 0; j < 32; j += 4) {
        ull a0, a1, a2, a3, a4, a5, a6, a7;
        {
            ulonglong2 b0 = *(const ulonglong2*)(bias + 0  + j);
            ulonglong2 b1 = *(const ulonglong2*)(bias + 32 + j);
            ulonglong2 b2 = *(const ulonglong2*)(bias + 64 + j);
            ulonglong2 b3 = *(const ulonglong2*)(bias + 96 + j);
            a0 = b0.x; a1 = b0.y; a2 = b1.x; a3 = b1.y;
            a4 = b2.x; a5 = b2.y; a6 = b3.x; a7 = b3.y;
        }
        #pragma unroll
        for (int k = 0; k < 16; k++) {
            ull p = pack2(xv[k], xv[k]);
            const float* w = wih_t + k * 128 + j;
            ulonglong2 w0 = *(const ulonglong2*)(w);
            ulonglong2 w1 = *(const ulonglong2*)(w + 32);
            ulonglong2 w2 = *(const ulonglong2*)(w + 64);
            ulonglong2 w3 = *(const ulonglong2*)(w + 96);
            a0 = fma2(w0.x, p, a0); a1 = fma2(w0.y, p, a1);
            a2 = fma2(w1.x, p, a2); a3 = fma2(w1.y, p, a3);
            a4 = fma2(w2.x, p, a4); a5 = fma2(w2.y, p, a5);
            a6 = fma2(w3.x, p, a6); a7 = fma2(w3.y, p, a7);
        }
        #pragma unroll
        for (int k = 0; k < 32; k++) {
            ull p = pack2(h[k], h[k]);
            const float* w = whh_t + k * 128 + j;
            ulonglong2 w0 = *(const ulonglong2*)(w);
            ulonglong2 w1 = *(const ulonglong2*)(w + 32);
            ulonglong2 w2 = *(const ulonglong2*)(w + 64);
            ulonglong2 w3 = *(const ulonglong2*)(w + 96);
            a0 = fma2(w0.x, p, a0); a1 = fma2(w0.y, p, a1);
            a2 = fma2(w1.x, p, a2); a3 = fma2(w1.y, p, a3);
            a4 = fma2(w2.x, p, a4); a5 = fma2(w2.y, p, a5);
            a6 = fma2(w3.x, p, a6); a7 = fma2(w3.y, p, a7);
        }
        float2 i01 = unpack2(a0), i23 = unpack2(a1);
        float2 f01 = unpack2(a2), f23 = unpack2(a3);
        float2 g01 = unpack2(a4), g23 = unpack2(a5);
        float2 o01 = unpack2(a6), o23 = unpack2(a7);
        float iv[4] = {i01.x, i01.y, i23.x, i23.y};
        float fv[4] = {f01.x, f01.y, f23.x, f23.y};
        float gv[4] = {g01.x, g01.y, g23.x, g23.y};
        float ov[4] = {o01.x, o01.y, o23.x, o23.y};
        #pragma unroll
        for (int q = 0; q < 4; q++) {
            float cc = sigf(fv[q]) * cv[j + q] + sigf(iv[q]) * tanha(gv[q]);
            float hv = sigf(ov[q]) * tanha(cc);
            s += hv * __ldg(&attw[j + q]);
        }
    }
}

__global__ void __launch_bounds__(128)
k_lstm(const float* __restrict__ wihF, const float* __restrict__ whhF,
       const float* __restrict__ bF,
       const float* __restrict__ wihB, const float* __restrict__ whhB,
       const float* __restrict__ bB,
       const float* __restrict__ attw)
{
    __shared__ __align__(16) float ws[12288];   // exactly 48 KB
    int tid = threadIdx.x;
    for (int i = tid; i < 2048; i += 128) {
        int jj = i >> 4, kk = i & 15;
        ws[kk * 128 + jj]        = wihF[i];
        ws[6144 + kk * 128 + jj] = wihB[i];
    }
    for (int i = tid; i < 4096; i += 128) {
        int jj = i >> 5, kk = i & 31;
        ws[2048 + kk * 128 + jj] = whhF[i];
        ws[8192 + kk * 128 + jj] = whhB[i];
    }
    __syncthreads();
    int v = blockIdx.x * 128 + tid;
    if (v >= NN) return;

    float x1v[16], x2v[16];
    {
        const float4* p1 = (const float4*)(g_x1 + v * 16);
        const float4* p2 = (const float4*)(g_x2 + v * 16);
        #pragma unroll
        for (int q = 0; q < 4; q++) {
            float4 t1 = p1[q];
            x1v[4 * q + 0] = t1.x; x1v[4 * q + 1] = t1.y;
            x1v[4 * q + 2] = t1.z; x1v[4 * q + 3] = t1.w;
            float4 t2 = p2[q];
            x2v[4 * q + 0] = t2.x; x2v[4 * q + 1] = t2.y;
            x2v[4 * q + 2] = t2.z; x2v[4 * q + 3] = t2.w;
        }
    }

    float h[32], cvs[32];
    float s0 = 0.f, s1 = 0.f;

    cell_first (ws,        bF, x1v, h, cvs, attw,      s0);              // hf0
    cell_second(ws, ws + 2048, bF, x2v, h, cvs, attw,  s1);              // hf1
    cell_first (ws + 6144, bB, x2v, h, cvs, attw + 32, s1);              // hb1
    cell_second(ws + 6144, ws + 8192, bB, x1v, h, cvs, attw + 32, s0);   // hb0

    // softmax over the 2 scores (att_b cancels)
    float m = fmaxf(s0, s1);
    float e0 = __expf(s0 - m), e1 = __expf(s1 - m);
    float inv = __fdividef(1.f, e0 + e1);
    float a0 = e0 * inv, a1 = e1 * inv;
    float dv = g_dinv[v];
    float* o = g_hs + v * 16;
    #pragma unroll
    for (int q = 0; q < 4; q++) {
        float4 r;
        r.x = dv * (a0 * x1v[4 * q + 0] + a1 * x2v[4 * q + 0]);
        r.y = dv * (a0 * x1v[4 * q + 1] + a1 * x2v[4 * q + 1]);
        r.z = dv * (a0 * x1v[4 * q + 2] + a1 * x2v[4 * q + 2]);
        r.w = dv * (a0 * x1v[4 * q + 3] + a1 * x2v[4 * q + 3]);
        *(float4*)(o + 4 * q) = r;
    }
}

// ---------------- 9) APPNP agg + linear + log_softmax ----------------
__global__ void k_out(const float* __restrict__ linw, const float* __restrict__ linb,
                      float* __restrict__ out)
{
    __shared__ float LW[640];
    __shared__ float LB[40];
    int tid = threadIdx.x;
    for (int i = tid; i < 640; i += 256) LW[i] = linw[i];
    if (tid < 40) LB[tid] = linb[tid];
    __syncthreads();

    int v = blockIdx.x * 16 + (tid >> 4);
    int j = tid & 15;
    float hval = gather_sum(v, j, g_hs);

    unsigned gb = (tid & 31) & 16;   // lane base of this node's 16-group
    float l0 = LB[j];
    float l1 = LB[j + 16];
    float l2 = (j < 8) ? LB[j + 32] : -1e30f;
    #pragma unroll
    for (int k = 0; k < 16; k++) {
        float hk = __shfl_sync(0xffffffffu, hval, gb + k);
        l0 = fmaf(hk, LW[k * 40 + j], l0);
        l1 = fmaf(hk, LW[k * 40 + j + 16], l1);
        if (j < 8) l2 = fmaf(hk, LW[k * 40 + j + 32], l2);
    }
    // group max over the 40 logits
    float m = fmaxf(l0, l1);
    if (j < 8) m = fmaxf(m, l2);
    #pragma unroll
    for (int off = 8; off > 0; off >>= 1)
        m = fmaxf(m, __shfl_xor_sync(0xffffffffu, m, off));
    float ssum = __expf(l0 - m) + __expf(l1 - m) + ((j < 8) ? __expf(l2 - m) : 0.f);
    #pragma unroll
    for (int off = 8; off > 0; off >>= 1)
        ssum += __shfl_xor_sync(0xffffffffu, ssum, off);
    float lse = m + __logf(ssum);

    out[v * 40 + j]      = l0 - lse;
    out[v * 40 + j + 16] = l1 - lse;
    if (j < 8) out[v * 40 + j + 32] = l2 - lse;
}

// ---------------- launch ----------------
extern "C" void kernel_launch(void* const* d_in, const int* in_sizes, int n_in,
                              void* d_out, int out_size) {
    const float* x     = (const float*)d_in[0];
    const void*  edges = d_in[1];
    const float* W1    = (const float*)d_in[2];
    const float* b1    = (const float*)d_in[3];
    const float* W2    = (const float*)d_in[4];
    const float* b2    = (const float*)d_in[5];
    const float* wihF  = (const float*)d_in[6];
    const float* whhF  = (const float*)d_in[7];
    const float* bF    = (const float*)d_in[8];
    const float* wihB  = (const float*)d_in[9];
    const float* whhB  = (const float*)d_in[10];
    const float* bB    = (const float*)d_in[11];
    const float* attw  = (const float*)d_in[12];
    const float* linw  = (const float*)d_in[14];
    const float* linb  = (const float*)d_in[15];
    float* out = (float*)d_out;

    k_init<<<(NN + 255) / 256, 256>>>((const unsigned*)edges);
    k_deg<<<NE / 256, 256>>>(edges);
    k_part<<<196, 512>>>();
    k_scanpart<<<1, 256>>>();
    k_rowptr<<<196, 512>>>();
    k_scatter<<<NE / 256, 256>>>(edges);
    k_xw1<<<(NN + 63) / 64, 256>>>(x, W1);
    k_agg1<<<NN / 16, 256>>>(b1, W2);
    k_agg2<<<NN / 16, 256>>>(b2);
    k_lstm<<<(NN + 127) / 128, 128>>>(wihF, whhF, bF, wihB, whhB, bB, attw);
    k_out<<<NN / 16, 256>>>(linw, linb, out);
}

// round 8
// speedup vs baseline: 1.2649x; 1.0259x over previous
#include <cuda_runtime.h>
#include <cuda_bf16.h>

#define NN 100000
#define NE 3200000

typedef unsigned long long ull;

// ---------------- scratch (static device arrays; no allocs) ----------------
__device__ int   g_is64;
__device__ int   g_hist[NN];
__device__ int   g_rowptr[NN + 1];
__device__ int   g_cursor[NN];
__device__ int   g_col[NE];
__device__ int   g_part[256];
__device__ float g_dinv[NN];
__device__ float g_h0s[NN * 16];   // dinv-scaled x@W1
__device__ float g_x1 [NN * 16];   // relu layer-1 output (raw)
__device__ float g_h1s[NN * 16];   // dinv-scaled x1@W2
__device__ float g_x2 [NN * 16];   // relu layer-2 output (raw)
__device__ float g_hs [NN * 16];   // dinv-scaled JK output

// ---------------- helpers ----------------
__device__ __forceinline__ float tanha(float x) {
    float y;
    asm("tanh.approx.f32 %0, %1;" : "=f"(y) : "f"(x));
    return y;
}
__device__ __forceinline__ float sigf(float x) {
    return fmaf(0.5f, tanha(0.5f * x), 0.5f);
}
__device__ __forceinline__ ull fma2(ull a, ull b, ull c) {
    ull d;
    asm("fma.rn.f32x2 %0, %1, %2, %3;" : "=l"(d) : "l"(a), "l"(b), "l"(c));
    return d;
}
__device__ __forceinline__ ull pack2(float a, float b) {
    ull r;
    asm("mov.b64 %0, {%1, %2};" : "=l"(r) : "f"(a), "f"(b));
    return r;
}
__device__ __forceinline__ float2 unpack2(ull v) {
    float2 r;
    asm("mov.b64 {%0, %1}, %2;" : "=f"(r.x), "=f"(r.y) : "l"(v));
    return r;
}

// ---------------- 1) hist zero + edge dtype detection (fused) ----------------
__global__ void k_init(const unsigned* __restrict__ e) {
    int i = blockIdx.x * 256 + threadIdx.x;
    if (i < NN) g_hist[i] = 0;
    if (blockIdx.x == 0) {
        __shared__ int found;
        if (threadIdx.x == 0) found = 0;
        __syncthreads();
        int f = 0;
        for (int k = threadIdx.x; k < 8192; k += 256)
            f |= (e[2 * k + 1] != 0u);
        if (f) atomicOr(&found, 1);
        __syncthreads();
        if (threadIdx.x == 0) g_is64 = found ? 0 : 1;
    }
}

// ---------------- 2) degree histogram (reads dst half only) ----------------
__global__ void k_deg(const void* __restrict__ edges) {
    int e = blockIdx.x * 256 + threadIdx.x;
    int d;
    if (g_is64) {
        d = (int)((const long long*)edges)[e + NE];
    } else {
        d = ((const int*)edges)[e + NE];
    }
    atomicAdd(&g_hist[d], 1);
}

// ---------------- 3) scan hist -> rowptr, dinv ----------------
__global__ void k_part() {
    __shared__ int sh[512];
    int t = threadIdx.x;
    int i = blockIdx.x * 512 + t;
    int v = (i < NN) ? g_hist[i] : 0;
    if (i < NN) g_dinv[i] = rsqrtf((float)v + 1.0f);
    sh[t] = v;
    __syncthreads();
    for (int off = 256; off > 0; off >>= 1) {
        if (t < off) sh[t] += sh[t + off];
        __syncthreads();
    }
    if (t == 0) g_part[blockIdx.x] = sh[0];
}

__global__ void k_scanpart() {
    __shared__ int sh[256];
    int t = threadIdx.x;
    int v = (t < 196) ? g_part[t] : 0;
    sh[t] = v;
    __syncthreads();
    for (int off = 1; off < 256; off <<= 1) {
        int add = (t >= off) ? sh[t - off] : 0;
        __syncthreads();
        sh[t] += add;
        __syncthreads();
    }
    if (t < 196) g_part[t] = sh[t] - v;   // exclusive
    if (t == 0) g_rowptr[NN] = NE;
}

__global__ void k_rowptr() {
    __shared__ int sh[512];
    int t = threadIdx.x;
    int i = blockIdx.x * 512 + t;
    int v = (i < NN) ? g_hist[i] : 0;
    sh[t] = v;
    __syncthreads();
    for (int off = 1; off < 512; off <<= 1) {
        int add = (t >= off) ? sh[t - off] : 0;
        __syncthreads();
        sh[t] += add;
        __syncthreads();
    }
    int excl = sh[t] - v + g_part[blockIdx.x];
    if (i < NN) {
        g_rowptr[i] = excl;
        g_cursor[i] = excl;
    }
}

// ---------------- 4) scatter edges into CSR (reads edges directly) ----------
__global__ void k_scatter(const void* __restrict__ edges) {
    int e = blockIdx.x * 256 + threadIdx.x;
    int s, d;
    if (g_is64) {
        const long long* p = (const long long*)edges;
        s = (int)p[e];
        d = (int)p[e + NE];
    } else {
        const int* p = (const int*)edges;
        s = p[e];
        d = p[e + NE];
    }
    int pos = atomicAdd(&g_cursor[d], 1);
    g_col[pos] = s;
}

// ---------------- 5) h0s = dinv[v] * (x @ W1) ----------------
__global__ void __launch_bounds__(256) k_xw1(const float* __restrict__ x,
                                             const float* __restrict__ W1) {
    __shared__ __align__(16) float Wsh[512 * 16];   // 32 KB
    __shared__ __align__(16) float xsh[64 * 36];    // 64 rows x 32 k, padded
    int t = threadIdx.x;
    for (int i = t; i < 8192; i += 256) Wsh[i] = W1[i];
    int row0 = blockIdx.x * 64;
    int jq = t & 3;
    int r  = t >> 2;
    ull acc01 = 0ULL, acc23 = 0ULL;
    for (int kt = 0; kt < 512; kt += 32) {
        __syncthreads();
        for (int idx = t; idx < 512; idx += 256) {
            int rr = idx >> 3, kq = idx & 7;
            int grow = row0 + rr;
            float4 v = (grow < NN) ? *(const float4*)&x[grow * 512 + kt + kq * 4]
                                   : make_float4(0.f, 0.f, 0.f, 0.f);
            *(float4*)&xsh[rr * 36 + kq * 4] = v;
        }
        __syncthreads();
        #pragma unroll
        for (int k = 0; k < 32; k += 4) {
            float4 xv = *(float4*)&xsh[r * 36 + k];
            ulonglong2 w;
            ull p;
            w = *(ulonglong2*)&Wsh[(kt + k + 0) * 16 + jq * 4];
            p = pack2(xv.x, xv.x);
            acc01 = fma2(w.x, p, acc01); acc23 = fma2(w.y, p, acc23);
            w = *(ulonglong2*)&Wsh[(kt + k + 1) * 16 + jq * 4];
            p = pack2(xv.y, xv.y);
            acc01 = fma2(w.x, p, acc01); acc23 = fma2(w.y, p, acc23);
            w = *(ulonglong2*)&Wsh[(kt + k + 2) * 16 + jq * 4];
            p = pack2(xv.z, xv.z);
            acc01 = fma2(w.x, p, acc01); acc23 = fma2(w.y, p, acc23);
            w = *(ulonglong2*)&Wsh[(kt + k + 3) * 16 + jq * 4];
            p = pack2(xv.w, xv.w);
            acc01 = fma2(w.x, p, acc01); acc23 = fma2(w.y, p, acc23);
        }
    }
    int row = row0 + r;
    if (row < NN) {
        float dv = g_dinv[row];
        float2 a01 = unpack2(acc01), a23 = unpack2(acc23);
        float4 res;
        res.x = dv * a01.x; res.y = dv * a01.y;
        res.z = dv * a23.x; res.w = dv * a23.y;
        *(float4*)&g_h0s[row * 16 + jq * 4] = res;
    }
}

// ---------------- gather core (MLP=16 via 4 independent partials) ----------
__device__ __forceinline__ float gather_sum(int v, int j, const float* __restrict__ in) {
    int b = g_rowptr[v], e = g_rowptr[v + 1];
    float acc = in[v * 16 + j];          // self-loop term (already dinv-scaled)
    int i = b;
    for (; i + 16 <= e; i += 16) {
        float t0 = 0.f, t1 = 0.f, t2 = 0.f, t3 = 0.f;
        #pragma unroll
        for (int k = 0; k < 16; k += 4) {
            int s0 = g_col[i + k],     s1 = g_col[i + k + 1];
            int s2 = g_col[i + k + 2], s3 = g_col[i + k + 3];
            t0 += in[s0 * 16 + j]; t1 += in[s1 * 16 + j];
            t2 += in[s2 * 16 + j]; t3 += in[s3 * 16 + j];
        }
        acc += (t0 + t1) + (t2 + t3);
    }
    for (; i + 4 <= e; i += 4) {
        int s0 = g_col[i], s1 = g_col[i + 1], s2 = g_col[i + 2], s3 = g_col[i + 3];
        acc += (in[s0 * 16 + j] + in[s1 * 16 + j]) + (in[s2 * 16 + j] + in[s3 * 16 + j]);
    }
    for (; i < e; i++) acc += in[g_col[i] * 16 + j];
    return g_dinv[v] * acc;
}

// ---------------- 6) agg1 + bias + relu, fused x1@W2 ----------------
__global__ void k_agg1(const float* __restrict__ b1, const float* __restrict__ W2) {
    __shared__ float W2s[256];
    int tid = threadIdx.x;
    W2s[tid] = W2[tid];
    __syncthreads();
    int v = blockIdx.x * 16 + (tid >> 4);
    int j = tid & 15;
    float val = gather_sum(v, j, g_h0s);
    float x1v = fmaxf(val + b1[j], 0.f);
    g_x1[v * 16 + j] = x1v;
    unsigned gb = (tid & 31) & 16;
    float h1 = 0.f;
    #pragma unroll
    for (int k = 0; k < 16; k++) {
        float xk = __shfl_sync(0xffffffffu, x1v, gb + k);
        h1 = fmaf(xk, W2s[k * 16 + j], h1);
    }
    g_h1s[v * 16 + j] = g_dinv[v] * h1;
}

// ---------------- 7) agg2 + bias + relu ----------------
__global__ void k_agg2(const float* __restrict__ b2) {
    int tid = threadIdx.x;
    int v = blockIdx.x * 16 + (tid >> 4);
    int j = tid & 15;
    float val = gather_sum(v, j, g_h1s);
    g_x2[v * 16 + j] = fmaxf(val + b2[j], 0.f);
}

// ---------------- 8) JK bidirectional LSTM + attention ----------------
// Shared weight layout (transposed, j-contiguous per k) -> exactly 48 KB:
//   [0:2048)      F w_ih^T     ws[k*128 + j] = w_ih[j][k]
//   [2048:6144)   F w_hh^T
//   [6144:8192)   B w_ih^T
//   [8192:12288)  B w_hh^T
// Biases + attw stay in gmem (tiny, L1-hot). x vectors reloaded per cell
// (L1/L2-hot) to keep persistent regs low; 256 thr x 2 blocks/SM -> <=128 regs.

__device__ __forceinline__ void cell_first(
    const float* __restrict__ wih_t, const float* __restrict__ bias,
    const float* __restrict__ xg, float* __restrict__ h, float* __restrict__ cv,
    const float* __restrict__ attw, float& s)
{
    float xv[16];
    #pragma unroll
    for (int q = 0; q < 4; q++) {
        float4 t = *(const float4*)(xg + 4 * q);
        xv[4 * q + 0] = t.x; xv[4 * q + 1] = t.y;
        xv[4 * q + 2] = t.z; xv[4 * q + 3] = t.w;
    }
    #pragma unroll 1
    for (int j = 0; j < 32; j += 4) {
        ull a0, a1, a2, a3, a4, a5, a6, a7;
        {
            ulonglong2 b0 = *(const ulonglong2*)(bias + 0  + j);
            ulonglong2 b1 = *(const ulonglong2*)(bias + 32 + j);
            ulonglong2 b2 = *(const ulonglong2*)(bias + 64 + j);
            ulonglong2 b3 = *(const ulonglong2*)(bias + 96 + j);
            a0 = b0.x; a1 = b0.y; a2 = b1.x; a3 = b1.y;
            a4 = b2.x; a5 = b2.y; a6 = b3.x; a7 = b3.y;
        }
        #pragma unroll
        for (int k = 0; k < 16; k++) {
            ull p = pack2(xv[k], xv[k]);
            const float* w = wih_t + k * 128 + j;
            ulonglong2 w0 = *(const ulonglong2*)(w);
            ulonglong2 w1 = *(const ulonglong2*)(w + 32);
            ulonglong2 w2 = *(const ulonglong2*)(w + 64);
            ulonglong2 w3 = *(const ulonglong2*)(w + 96);
            a0 = fma2(w0.x, p, a0); a1 = fma2(w0.y, p, a1);
            a2 = fma2(w1.x, p, a2); a3 = fma2(w1.y, p, a3);
            a4 = fma2(w2.x, p, a4); a5 = fma2(w2.y, p, a5);
            a6 = fma2(w3.x, p, a6); a7 = fma2(w3.y, p, a7);
        }
        float2 i01 = unpack2(a0), i23 = unpack2(a1);
        float2 g01 = unpack2(a4), g23 = unpack2(a5);
        float2 o01 = unpack2(a6), o23 = unpack2(a7);
        float iv[4] = {i01.x, i01.y, i23.x, i23.y};
        float gv[4] = {g01.x, g01.y, g23.x, g23.y};
        float ov[4] = {o01.x, o01.y, o23.x, o23.y};
        #pragma unroll
        for (int q = 0; q < 4; q++) {
            float cc = sigf(iv[q]) * tanha(gv[q]);     // f-gate * 0 dropped
            cv[j + q] = cc;
            float hv = sigf(ov[q]) * tanha(cc);
            h[j + q] = hv;
            s += hv * __ldg(&attw[j + q]);
        }
    }
}

__device__ __forceinline__ void cell_second(
    const float* __restrict__ wih_t, const float* __restrict__ whh_t,
    const float* __restrict__ bias,
    const float* __restrict__ xg, const float* __restrict__ h,
    const float* __restrict__ cv,
    const float* __restrict__ attw, float& s)
{
    float xv[16];
    #pragma unroll
    for (int q = 0; q < 4; q++) {
        float4 t = *(const float4*)(xg + 4 * q);
        xv[4 * q + 0] = t.x; xv[4 * q + 1] = t.y;
        xv[4 * q + 2] = t.z; xv[4 * q + 3] = t.w;
    }
    #pragma unroll 1
    for (int j = 0; j < 32; j += 4) {
        ull a0, a1, a2, a3, a4, a5, a6, a7;
        {
            ulonglong2 b0 = *(const ulonglong2*)(bias + 0  + j);
            ulonglong2 b1 = *(const ulonglong2*)(bias + 32 + j);
            ulonglong2 b2 = *(const ulonglong2*)(bias + 64 + j);
            ulonglong2 b3 = *(const ulonglong2*)(bias + 96 + j);
            a0 = b0.x; a1 = b0.y; a2 = b1.x; a3 = b1.y;
            a4 = b2.x; a5 = b2.y; a6 = b3.x; a7 = b3.y;
        }
        #pragma unroll
        for (int k = 0; k < 16; k++) {
            ull p = pack2(xv[k], xv[k]);
            const float* w = wih_t + k * 128 + j;
            ulonglong2 w0 = *(const ulonglong2*)(w);
            ulonglong2 w1 = *(const ulonglong2*)(w + 32);
            ulonglong2 w2 = *(const ulonglong2*)(w + 64);
            ulonglong2 w3 = *(const ulonglong2*)(w + 96);
            a0 = fma2(w0.x, p, a0); a1 = fma2(w0.y, p, a1);
            a2 = fma2(w1.x, p, a2); a3 = fma2(w1.y, p, a3);
            a4 = fma2(w2.x, p, a4); a5 = fma2(w2.y, p, a5);
            a6 = fma2(w3.x, p, a6); a7 = fma2(w3.y, p, a7);
        }
        #pragma unroll
        for (int k = 0; k < 32; k++) {
            ull p = pack2(h[k], h[k]);
            const float* w = whh_t + k * 128 + j;
            ulonglong2 w0 = *(const ulonglong2*)(w);
            ulonglong2 w1 = *(const ulonglong2*)(w + 32);
            ulonglong2 w2 = *(const ulonglong2*)(w + 64);
            ulonglong2 w3 = *(const ulonglong2*)(w + 96);
            a0 = fma2(w0.x, p, a0); a1 = fma2(w0.y, p, a1);
            a2 = fma2(w1.x, p, a2); a3 = fma2(w1.y, p, a3);
            a4 = fma2(w2.x, p, a4); a5 = fma2(w2.y, p, a5);
            a6 = fma2(w3.x, p, a6); a7 = fma2(w3.y, p, a7);
        }
        float2 i01 = unpack2(a0), i23 = unpack2(a1);
        float2 f01 = unpack2(a2), f23 = unpack2(a3);
        float2 g01 = unpack2(a4), g23 = unpack2(a5);
        float2 o01 = unpack2(a6), o23 = unpack2(a7);
        float iv[4] = {i01.x, i01.y, i23.x, i23.y};
        float fv[4] = {f01.x, f01.y, f23.x, f23.y};
        float gv[4] = {g01.x, g01.y, g23.x, g23.y};
        float ov[4] = {o01.x, o01.y, o23.x, o23.y};
        #pragma unroll
        for (int q = 0; q < 4; q++) {
            float cc = sigf(fv[q]) * cv[j + q] + sigf(iv[q]) * tanha(gv[q]);
            float hv = sigf(ov[q]) * tanha(cc);
            s += hv * __ldg(&attw[j + q]);
        }
    }
}

__global__ void __launch_bounds__(256, 2)
k_lstm(const float* __restrict__ wihF, const float* __restrict__ whhF,
       const float* __restrict__ bF,
       const float* __restrict__ wihB, const float* __restrict__ whhB,
       const float* __restrict__ bB,
       const float* __restrict__ attw)
{
    __shared__ __align__(16) float ws[12288];   // exactly 48 KB
    int tid = threadIdx.x;
    for (int i = tid; i < 2048; i += 256) {
        int jj = i >> 4, kk = i & 15;
        ws[kk * 128 + jj]        = wihF[i];
        ws[6144 + kk * 128 + jj] = wihB[i];
    }
    for (int i = tid; i < 4096; i += 256) {
        int jj = i >> 5, kk = i & 31;
        ws[2048 + kk * 128 + jj] = whhF[i];
        ws[8192 + kk * 128 + jj] = whhB[i];
    }
    __syncthreads();
    int v = blockIdx.x * 256 + tid;
    if (v >= NN) return;

    const float* x1g = g_x1 + v * 16;
    const float* x2g = g_x2 + v * 16;
    float h[32], cvs[32];
    float s0 = 0.f, s1 = 0.f;

    cell_first (ws,        bF, x1g, h, cvs, attw,      s0);              // hf0
    cell_second(ws, ws + 2048, bF, x2g, h, cvs, attw,  s1);              // hf1
    cell_first (ws + 6144, bB, x2g, h, cvs, attw + 32, s1);              // hb1
    cell_second(ws + 6144, ws + 8192, bB, x1g, h, cvs, attw + 32, s0);   // hb0

    // softmax over the 2 scores (att_b cancels)
    float m = fmaxf(s0, s1);
    float e0 = __expf(s0 - m), e1 = __expf(s1 - m);
    float inv = __fdividef(1.f, e0 + e1);
    float a0 = e0 * inv, a1 = e1 * inv;
    float dv = g_dinv[v];
    float* o = g_hs + v * 16;
    #pragma unroll
    for (int q = 0; q < 4; q++) {
        float4 t1 = *(const float4*)(x1g + 4 * q);
        float4 t2 = *(const float4*)(x2g + 4 * q);
        float4 r;
        r.x = dv * (a0 * t1.x + a1 * t2.x);
        r.y = dv * (a0 * t1.y + a1 * t2.y);
        r.z = dv * (a0 * t1.z + a1 * t2.z);
        r.w = dv * (a0 * t1.w + a1 * t2.w);
        *(float4*)(o + 4 * q) = r;
    }
}

// ---------------- 9) APPNP agg + linear + log_softmax ----------------
__global__ void k_out(const float* __restrict__ linw, const float* __restrict__ linb,
                      float* __restrict__ out)
{
    __shared__ float LW[640];
    __shared__ float LB[40];
    int tid = threadIdx.x;
    for (int i = tid; i < 640; i += 256) LW[i] = linw[i];
    if (tid < 40) LB[tid] = linb[tid];
    __syncthreads();

    int v = blockIdx.x * 16 + (tid >> 4);
    int j = tid & 15;
    float hval = gather_sum(v, j, g_hs);

    unsigned gb = (tid & 31) & 16;   // lane base of this node's 16-group
    float l0 = LB[j];
    float l1 = LB[j + 16];
    float l2 = (j < 8) ? LB[j + 32] : -1e30f;
    #pragma unroll
    for (int k = 0; k < 16; k++) {
        float hk = __shfl_sync(0xffffffffu, hval, gb + k);
        l0 = fmaf(hk, LW[k * 40 + j], l0);
        l1 = fmaf(hk, LW[k * 40 + j + 16], l1);
        if (j < 8) l2 = fmaf(hk, LW[k * 40 + j + 32], l2);
    }
    // group max over the 40 logits
    float m = fmaxf(l0, l1);
    if (j < 8) m = fmaxf(m, l2);
    #pragma unroll
    for (int off = 8; off > 0; off >>= 1)
        m = fmaxf(m, __shfl_xor_sync(0xffffffffu, m, off));
    float ssum = __expf(l0 - m) + __expf(l1 - m) + ((j < 8) ? __expf(l2 - m) : 0.f);
    #pragma unroll
    for (int off = 8; off > 0; off >>= 1)
        ssum += __shfl_xor_sync(0xffffffffu, ssum, off);
    float lse = m + __logf(ssum);

    out[v * 40 + j]      = l0 - lse;
    out[v * 40 + j + 16] = l1 - lse;
    if (j < 8) out[v * 40 + j + 32] = l2 - lse;
}

// ---------------- launch (k_xw1 at slot 4 for ncu visibility) --------------
extern "C" void kernel_launch(void* const* d_in, const int* in_sizes, int n_in,
                              void* d_out, int out_size) {
    const float* x     = (const float*)d_in[0];
    const void*  edges = d_in[1];
    const float* W1    = (const float*)d_in[2];
    const float* b1    = (const float*)d_in[3];
    const float* W2    = (const float*)d_in[4];
    const float* b2    = (const float*)d_in[5];
    const float* wihF  = (const float*)d_in[6];
    const float* whhF  = (const float*)d_in[7];
    const float* bF    = (const float*)d_in[8];
    const float* wihB  = (const float*)d_in[9];
    const float* whhB  = (const float*)d_in[10];
    const float* bB    = (const float*)d_in[11];
    const float* attw  = (const float*)d_in[12];
    const float* linw  = (const float*)d_in[14];
    const float* linb  = (const float*)d_in[15];
    float* out = (float*)d_out;

    k_init<<<(NN + 255) / 256, 256>>>((const unsigned*)edges);
    k_deg<<<NE / 256, 256>>>(edges);
    k_part<<<196, 512>>>();
    k_xw1<<<(NN + 63) / 64, 256>>>(x, W1);       // slot 4 -> ncu captures this
    k_scanpart<<<1, 256>>>();
    k_rowptr<<<196, 512>>>();
    k_scatter<<<NE / 256, 256>>>(edges);
    k_agg1<<<NN / 16, 256>>>(b1, W2);
    k_agg2<<<NN / 16, 256>>>(b2);
    k_lstm<<<(NN + 255) / 256, 256>>>(wihF, whhF, bF, wihB, whhB, bB, attw);
    k_out<<<NN / 16, 256>>>(linw, linb, out);
}

// round 10
// speedup vs baseline: 1.4132x; 1.1172x over previous
#include <cuda_runtime.h>
#include <cuda_bf16.h>

#define NN 100000
#define NE 3200000

typedef unsigned long long ull;

// ---------------- scratch (static device arrays; no allocs) ----------------
__device__ int   g_is64;
__device__ int   g_hist[NN];
__device__ int   g_rowptr[NN + 1];
__device__ int   g_cursor[NN];
__device__ int   g_col[NE];
__device__ int   g_part[256];
__device__ float g_dinv[NN];
__device__ float g_h0s[NN * 16];   // dinv-scaled x@W1
__device__ float g_x1 [NN * 16];   // relu layer-1 output (raw)
__device__ float g_h1s[NN * 16];   // dinv-scaled x1@W2
__device__ float g_x2 [NN * 16];   // relu layer-2 output (raw)
__device__ float g_hs [NN * 16];   // dinv-scaled JK output

// ---------------- helpers ----------------
__device__ __forceinline__ float tanha(float x) {
    float y;
    asm("tanh.approx.f32 %0, %1;" : "=f"(y) : "f"(x));
    return y;
}
__device__ __forceinline__ float sigf(float x) {
    return fmaf(0.5f, tanha(0.5f * x), 0.5f);
}
__device__ __forceinline__ ull fma2(ull a, ull b, ull c) {
    ull d;
    asm("fma.rn.f32x2 %0, %1, %2, %3;" : "=l"(d) : "l"(a), "l"(b), "l"(c));
    return d;
}
__device__ __forceinline__ ull pack2(float a, float b) {
    ull r;
    asm("mov.b64 %0, {%1, %2};" : "=l"(r) : "f"(a), "f"(b));
    return r;
}
__device__ __forceinline__ float2 unpack2(ull v) {
    float2 r;
    asm("mov.b64 {%0, %1}, %2;" : "=f"(r.x), "=f"(r.y) : "l"(v));
    return r;
}

// ---------------- 1) hist zero + edge dtype detection (fused) ----------------
__global__ void k_init(const unsigned* __restrict__ e) {
    int i = blockIdx.x * 256 + threadIdx.x;
    if (i < NN) g_hist[i] = 0;
    if (blockIdx.x == 0) {
        __shared__ int found;
        if (threadIdx.x == 0) found = 0;
        __syncthreads();
        int f = 0;
        for (int k = threadIdx.x; k < 8192; k += 256)
            f |= (e[2 * k + 1] != 0u);
        if (f) atomicOr(&found, 1);
        __syncthreads();
        if (threadIdx.x == 0) g_is64 = found ? 0 : 1;
    }
}

// ---------------- 2) degree histogram (reads dst half only) ----------------
__global__ void k_deg(const void* __restrict__ edges) {
    int e = blockIdx.x * 256 + threadIdx.x;
    int d;
    if (g_is64) {
        d = (int)((const long long*)edges)[e + NE];
    } else {
        d = ((const int*)edges)[e + NE];
    }
    atomicAdd(&g_hist[d], 1);
}

// ---------------- 3) scan hist -> rowptr, dinv ----------------
__global__ void k_part() {
    __shared__ int sh[512];
    int t = threadIdx.x;
    int i = blockIdx.x * 512 + t;
    int v = (i < NN) ? g_hist[i] : 0;
    if (i < NN) g_dinv[i] = rsqrtf((float)v + 1.0f);
    sh[t] = v;
    __syncthreads();
    for (int off = 256; off > 0; off >>= 1) {
        if (t < off) sh[t] += sh[t + off];
        __syncthreads();
    }
    if (t == 0) g_part[blockIdx.x] = sh[0];
}

__global__ void k_scanpart() {
    __shared__ int sh[256];
    int t = threadIdx.x;
    int v = (t < 196) ? g_part[t] : 0;
    sh[t] = v;
    __syncthreads();
    for (int off = 1; off < 256; off <<= 1) {
        int add = (t >= off) ? sh[t - off] : 0;
        __syncthreads();
        sh[t] += add;
        __syncthreads();
    }
    if (t < 196) g_part[t] = sh[t] - v;   // exclusive
    if (t == 0) g_rowptr[NN] = NE;
}

__global__ void k_rowptr() {
    __shared__ int sh[512];
    int t = threadIdx.x;
    int i = blockIdx.x * 512 + t;
    int v = (i < NN) ? g_hist[i] : 0;
    sh[t] = v;
    __syncthreads();
    for (int off = 1; off < 512; off <<= 1) {
        int add = (t >= off) ? sh[t - off] : 0;
        __syncthreads();
        sh[t] += add;
        __syncthreads();
    }
    int excl = sh[t] - v + g_part[blockIdx.x];
    if (i < NN) {
        g_rowptr[i] = excl;
        g_cursor[i] = excl;
    }
}

// ---------------- 4) scatter edges into CSR (reads edges directly) ----------
__global__ void k_scatter(const void* __restrict__ edges) {
    int e = blockIdx.x * 256 + threadIdx.x;
    int s, d;
    if (g_is64) {
        const long long* p = (const long long*)edges;
        s = (int)p[e];
        d = (int)p[e + NE];
    } else {
        const int* p = (const int*)edges;
        s = p[e];
        d = p[e + NE];
    }
    int pos = atomicAdd(&g_cursor[d], 1);
    g_col[pos] = s;
}

// ---------------- 5) h0s = dinv[v] * (x @ W1) ----------------
// Thread = 2 rows x 16 cols. W1 in smem, read broadcast (all lanes same addr
// -> 1 wavefront per LDS.128). x streamed per-lane with LDG.128; each 128B
// line fully consumed by 8 consecutive loads of the same lane (L1-resident).
// Per k: 4 broadcast LDS + 16 FFMA2 -> FMA/wavefront bound instead of
// smem-crossbar bound. unroll 4 -> MLP~8 to hide the 1-in-8 DRAM misses.
__global__ void __launch_bounds__(128) k_xw1(const float* __restrict__ x,
                                             const float* __restrict__ W1) {
    __shared__ __align__(16) float Wsh[512 * 16];   // 32 KB
    int t = threadIdx.x;
    for (int i = t; i < 2048; i += 128)
        ((float4*)Wsh)[i] = ((const float4*)W1)[i];
    __syncthreads();

    int r0 = (blockIdx.x * 128 + t) * 2;   // two consecutive rows (NN even)
    if (r0 >= NN) return;
    const float4* xr0 = (const float4*)(x + (size_t)r0 * 512);
    const float4* xr1 = (const float4*)(x + (size_t)(r0 + 1) * 512);

    ull a0[8], a1[8];
    #pragma unroll
    for (int i = 0; i < 8; i++) { a0[i] = 0ULL; a1[i] = 0ULL; }

    #pragma unroll 4
    for (int kq = 0; kq < 128; kq++) {
        float4 v0 = xr0[kq];
        float4 v1 = xr1[kq];
        const float* wb = Wsh + kq * 64;
        float xs0[4] = {v0.x, v0.y, v0.z, v0.w};
        float xs1[4] = {v1.x, v1.y, v1.z, v1.w};
        #pragma unroll
        for (int s = 0; s < 4; s++) {
            const float* w = wb + s * 16;
            ulonglong2 wA = *(const ulonglong2*)(w);
            ulonglong2 wB = *(const ulonglong2*)(w + 4);
            ulonglong2 wC = *(const ulonglong2*)(w + 8);
            ulonglong2 wD = *(const ulonglong2*)(w + 12);
            ull p0 = pack2(xs0[s], xs0[s]);
            ull p1 = pack2(xs1[s], xs1[s]);
            a0[0] = fma2(wA.x, p0, a0[0]); a0[1] = fma2(wA.y, p0, a0[1]);
            a0[2] = fma2(wB.x, p0, a0[2]); a0[3] = fma2(wB.y, p0, a0[3]);
            a0[4] = fma2(wC.x, p0, a0[4]); a0[5] = fma2(wC.y, p0, a0[5]);
            a0[6] = fma2(wD.x, p0, a0[6]); a0[7] = fma2(wD.y, p0, a0[7]);
            a1[0] = fma2(wA.x, p1, a1[0]); a1[1] = fma2(wA.y, p1, a1[1]);
            a1[2] = fma2(wB.x, p1, a1[2]); a1[3] = fma2(wB.y, p1, a1[3]);
            a1[4] = fma2(wC.x, p1, a1[4]); a1[5] = fma2(wC.y, p1, a1[5]);
            a1[6] = fma2(wD.x, p1, a1[6]); a1[7] = fma2(wD.y, p1, a1[7]);
        }
    }

    float dv0 = g_dinv[r0];
    float dv1 = g_dinv[r0 + 1];
    float* o0 = g_h0s + (size_t)r0 * 16;
    float* o1 = o0 + 16;
    #pragma unroll
    for (int i = 0; i < 4; i++) {
        float2 u0 = unpack2(a0[2 * i]), u1 = unpack2(a0[2 * i + 1]);
        float4 r;
        r.x = dv0 * u0.x; r.y = dv0 * u0.y; r.z = dv0 * u1.x; r.w = dv0 * u1.y;
        *(float4*)(o0 + 4 * i) = r;
        float2 v0 = unpack2(a1[2 * i]), v1 = unpack2(a1[2 * i + 1]);
        float4 q;
        q.x = dv1 * v0.x; q.y = dv1 * v0.y; q.z = dv1 * v1.x; q.w = dv1 * v1.y;
        *(float4*)(o1 + 4 * i) = q;
    }
}

// ---------------- gather core (MLP=16 via 4 independent partials) ----------
__device__ __forceinline__ float gather_sum(int v, int j, const float* __restrict__ in) {
    int b = g_rowptr[v], e = g_rowptr[v + 1];
    float acc = in[v * 16 + j];          // self-loop term (already dinv-scaled)
    int i = b;
    for (; i + 16 <= e; i += 16) {
        float t0 = 0.f, t1 = 0.f, t2 = 0.f, t3 = 0.f;
        #pragma unroll
        for (int k = 0; k < 16; k += 4) {
            int s0 = g_col[i + k],     s1 = g_col[i + k + 1];
            int s2 = g_col[i + k + 2], s3 = g_col[i + k + 3];
            t0 += in[s0 * 16 + j]; t1 += in[s1 * 16 + j];
            t2 += in[s2 * 16 + j]; t3 += in[s3 * 16 + j];
        }
        acc += (t0 + t1) + (t2 + t3);
    }
    for (; i + 4 <= e; i += 4) {
        int s0 = g_col[i], s1 = g_col[i + 1], s2 = g_col[i + 2], s3 = g_col[i + 3];
        acc += (in[s0 * 16 + j] + in[s1 * 16 + j]) + (in[s2 * 16 + j] + in[s3 * 16 + j]);
    }
    for (; i < e; i++) acc += in[g_col[i] * 16 + j];
    return g_dinv[v] * acc;
}

// ---------------- 6) agg1 + bias + relu, fused x1@W2 ----------------
__global__ void k_agg1(const float* __restrict__ b1, const float* __restrict__ W2) {
    __shared__ float W2s[256];
    int tid = threadIdx.x;
    W2s[tid] = W2[tid];
    __syncthreads();
    int v = blockIdx.x * 16 + (tid >> 4);
    int j = tid & 15;
    float val = gather_sum(v, j, g_h0s);
    float x1v = fmaxf(val + b1[j], 0.f);
    g_x1[v * 16 + j] = x1v;
    unsigned gb = (tid & 31) & 16;
    float h1 = 0.f;
    #pragma unroll
    for (int k = 0; k < 16; k++) {
        float xk = __shfl_sync(0xffffffffu, x1v, gb + k);
        h1 = fmaf(xk, W2s[k * 16 + j], h1);
    }
    g_h1s[v * 16 + j] = g_dinv[v] * h1;
}

// ---------------- 7) agg2 + bias + relu ----------------
__global__ void k_agg2(const float* __restrict__ b2) {
    int tid = threadIdx.x;
    int v = blockIdx.x * 16 + (tid >> 4);
    int j = tid & 15;
    float val = gather_sum(v, j, g_h1s);
    g_x2[v * 16 + j] = fmaxf(val + b2[j], 0.f);
}

// ---------------- 8) JK bidirectional LSTM + attention ----------------
// Shared weight layout (transposed, j-contiguous per k) -> exactly 48 KB:
//   [0:2048)      F w_ih^T     ws[k*128 + j] = w_ih[j][k]
//   [2048:6144)   F w_hh^T
//   [6144:8192)   B w_ih^T
//   [8192:12288)  B w_hh^T
// Biases + attw stay in gmem (tiny, L1-hot). x vectors reloaded per cell
// (L1/L2-hot) to keep persistent regs low; 256 thr x 2 blocks/SM -> <=128 regs.

__device__ __forceinline__ void cell_first(
    const float* __restrict__ wih_t, const float* __restrict__ bias,
    const float* __restrict__ xg, float* __restrict__ h, float* __restrict__ cv,
    const float* __restrict__ attw, float& s)
{
    float xv[16];
    #pragma unroll
    for (int q = 0; q < 4; q++) {
        float4 t = *(const float4*)(xg + 4 * q);
        xv[4 * q + 0] = t.x; xv[4 * q + 1] = t.y;
        xv[4 * q + 2] = t.z; xv[4 * q + 3] = t.w;
    }
    #pragma unroll 1
    for (int j = 0; j < 32; j += 4) {
        ull a0, a1, a2, a3, a4, a5, a6, a7;
        {
            ulonglong2 b0 = *(const ulonglong2*)(bias + 0  + j);
            ulonglong2 b1 = *(const ulonglong2*)(bias + 32 + j);
            ulonglong2 b2 = *(const ulonglong2*)(bias + 64 + j);
            ulonglong2 b3 = *(const ulonglong2*)(bias + 96 + j);
            a0 = b0.x; a1 = b0.y; a2 = b1.x; a3 = b1.y;
            a4 = b2.x; a5 = b2.y; a6 = b3.x; a7 = b3.y;
        }
        #pragma unroll
        for (int k = 0; k < 16; k++) {
            ull p = pack2(xv[k], xv[k]);
            const float* w = wih_t + k * 128 + j;
            ulonglong2 w0 = *(const ulonglong2*)(w);
            ulonglong2 w1 = *(const ulonglong2*)(w + 32);
            ulonglong2 w2 = *(const ulonglong2*)(w + 64);
            ulonglong2 w3 = *(const ulonglong2*)(w + 96);
            a0 = fma2(w0.x, p, a0); a1 = fma2(w0.y, p, a1);
            a2 = fma2(w1.x, p, a2); a3 = fma2(w1.y, p, a3);
            a4 = fma2(w2.x, p, a4); a5 = fma2(w2.y, p, a5);
            a6 = fma2(w3.x, p, a6); a7 = fma2(w3.y, p, a7);
        }
        float2 i01 = unpack2(a0), i23 = unpack2(a1);
        float2 g01 = unpack2(a4), g23 = unpack2(a5);
        float2 o01 = unpack2(a6), o23 = unpack2(a7);
        float iv[4] = {i01.x, i01.y, i23.x, i23.y};
        float gv[4] = {g01.x, g01.y, g23.x, g23.y};
        float ov[4] = {o01.x, o01.y, o23.x, o23.y};
        #pragma unroll
        for (int q = 0; q < 4; q++) {
            float cc = sigf(iv[q]) * tanha(gv[q]);     // f-gate * 0 dropped
            cv[j + q] = cc;
            float hv = sigf(ov[q]) * tanha(cc);
            h[j + q] = hv;
            s += hv * __ldg(&attw[j + q]);
        }
    }
}

__device__ __forceinline__ void cell_second(
    const float* __restrict__ wih_t, const float* __restrict__ whh_t,
    const float* __restrict__ bias,
    const float* __restrict__ xg, const float* __restrict__ h,
    const float* __restrict__ cv,
    const float* __restrict__ attw, float& s)
{
    float xv[16];
    #pragma unroll
    for (int q = 0; q < 4; q++) {
        float4 t = *(const float4*)(xg + 4 * q);
        xv[4 * q + 0] = t.x; xv[4 * q + 1] = t.y;
        xv[4 * q + 2] = t.z; xv[4 * q + 3] = t.w;
    }
    #pragma unroll 1
    for (int j = 0; j < 32; j += 4) {
        ull a0, a1, a2, a3, a4, a5, a6, a7;
        {
            ulonglong2 b0 = *(const ulonglong2*)(bias + 0  + j);
            ulonglong2 b1 = *(const ulonglong2*)(bias + 32 + j);
            ulonglong2 b2 = *(const ulonglong2*)(bias + 64 + j);
            ulonglong2 b3 = *(const ulonglong2*)(bias + 96 + j);
            a0 = b0.x; a1 = b0.y; a2 = b1.x; a3 = b1.y;
            a4 = b2.x; a5 = b2.y; a6 = b3.x; a7 = b3.y;
        }
        #pragma unroll
        for (int k = 0; k < 16; k++) {
            ull p = pack2(xv[k], xv[k]);
            const float* w = wih_t + k * 128 + j;
            ulonglong2 w0 = *(const ulonglong2*)(w);
            ulonglong2 w1 = *(const ulonglong2*)(w + 32);
            ulonglong2 w2 = *(const ulonglong2*)(w + 64);
            ulonglong2 w3 = *(const ulonglong2*)(w + 96);
            a0 = fma2(w0.x, p, a0); a1 = fma2(w0.y, p, a1);
            a2 = fma2(w1.x, p, a2); a3 = fma2(w1.y, p, a3);
            a4 = fma2(w2.x, p, a4); a5 = fma2(w2.y, p, a5);
            a6 = fma2(w3.x, p, a6); a7 = fma2(w3.y, p, a7);
        }
        #pragma unroll
        for (int k = 0; k < 32; k++) {
            ull p = pack2(h[k], h[k]);
            const float* w = whh_t + k * 128 + j;
            ulonglong2 w0 = *(const ulonglong2*)(w);
            ulonglong2 w1 = *(const ulonglong2*)(w + 32);
            ulonglong2 w2 = *(const ulonglong2*)(w + 64);
            ulonglong2 w3 = *(const ulonglong2*)(w + 96);
            a0 = fma2(w0.x, p, a0); a1 = fma2(w0.y, p, a1);
            a2 = fma2(w1.x, p, a2); a3 = fma2(w1.y, p, a3);
            a4 = fma2(w2.x, p, a4); a5 = fma2(w2.y, p, a5);
            a6 = fma2(w3.x, p, a6); a7 = fma2(w3.y, p, a7);
        }
        float2 i01 = unpack2(a0), i23 = unpack2(a1);
        float2 f01 = unpack2(a2), f23 = unpack2(a3);
        float2 g01 = unpack2(a4), g23 = unpack2(a5);
        float2 o01 = unpack2(a6), o23 = unpack2(a7);
        float iv[4] = {i01.x, i01.y, i23.x, i23.y};
        float fv[4] = {f01.x, f01.y, f23.x, f23.y};
        float gv[4] = {g01.x, g01.y, g23.x, g23.y};
        float ov[4] = {o01.x, o01.y, o23.x, o23.y};
        #pragma unroll
        for (int q = 0; q < 4; q++) {
            float cc = sigf(fv[q]) * cv[j + q] + sigf(iv[q]) * tanha(gv[q]);
            float hv = sigf(ov[q]) * tanha(cc);
            s += hv * __ldg(&attw[j + q]);
        }
    }
}

__global__ void __launch_bounds__(256, 2)
k_lstm(const float* __restrict__ wihF, const float* __restrict__ whhF,
       const float* __restrict__ bF,
       const float* __restrict__ wihB, const float* __restrict__ whhB,
       const float* __restrict__ bB,
       const float* __restrict__ attw)
{
    __shared__ __align__(16) float ws[12288];   // exactly 48 KB
    int tid = threadIdx.x;
    for (int i = tid; i < 2048; i += 256) {
        int jj = i >> 4, kk = i & 15;
        ws[kk * 128 + jj]        = wihF[i];
        ws[6144 + kk * 128 + jj] = wihB[i];
    }
    for (int i = tid; i < 4096; i += 256) {
        int jj = i >> 5, kk = i & 31;
        ws[2048 + kk * 128 + jj] = whhF[i];
        ws[8192 + kk * 128 + jj] = whhB[i];
    }
    __syncthreads();
    int v = blockIdx.x * 256 + tid;
    if (v >= NN) return;

    const float* x1g = g_x1 + v * 16;
    const float* x2g = g_x2 + v * 16;
    float h[32], cvs[32];
    float s0 = 0.f, s1 = 0.f;

    cell_first (ws,        bF, x1g, h, cvs, attw,      s0);              // hf0
    cell_second(ws, ws + 2048, bF, x2g, h, cvs, attw,  s1);              // hf1
    cell_first (ws + 6144, bB, x2g, h, cvs, attw + 32, s1);              // hb1
    cell_second(ws + 6144, ws + 8192, bB, x1g, h, cvs, attw + 32, s0);   // hb0

    // softmax over the 2 scores (att_b cancels)
    float m = fmaxf(s0, s1);
    float e0 = __expf(s0 - m), e1 = __expf(s1 - m);
    float inv = __fdividef(1.f, e0 + e1);
    float a0 = e0 * inv, a1 = e1 * inv;
    float dv = g_dinv[v];
    float* o = g_hs + v * 16;
    #pragma unroll
    for (int q = 0; q < 4; q++) {
        float4 t1 = *(const float4*)(x1g + 4 * q);
        float4 t2 = *(const float4*)(x2g + 4 * q);
        float4 r;
        r.x = dv * (a0 * t1.x + a1 * t2.x);
        r.y = dv * (a0 * t1.y + a1 * t2.y);
        r.z = dv * (a0 * t1.z + a1 * t2.z);
        r.w = dv * (a0 * t1.w + a1 * t2.w);
        *(float4*)(o + 4 * q) = r;
    }
}

// ---------------- 9) APPNP agg + linear + log_softmax ----------------
__global__ void k_out(const float* __restrict__ linw, const float* __restrict__ linb,
                      float* __restrict__ out)
{
    __shared__ float LW[640];
    __shared__ float LB[40];
    int tid = threadIdx.x;
    for (int i = tid; i < 640; i += 256) LW[i] = linw[i];
    if (tid < 40) LB[tid] = linb[tid];
    __syncthreads();

    int v = blockIdx.x * 16 + (tid >> 4);
    int j = tid & 15;
    float hval = gather_sum(v, j, g_hs);

    unsigned gb = (tid & 31) & 16;   // lane base of this node's 16-group
    float l0 = LB[j];
    float l1 = LB[j + 16];
    float l2 = (j < 8) ? LB[j + 32] : -1e30f;
    #pragma unroll
    for (int k = 0; k < 16; k++) {
        float hk = __shfl_sync(0xffffffffu, hval, gb + k);
        l0 = fmaf(hk, LW[k * 40 + j], l0);
        l1 = fmaf(hk, LW[k * 40 + j + 16], l1);
        if (j < 8) l2 = fmaf(hk, LW[k * 40 + j + 32], l2);
    }
    // group max over the 40 logits
    float m = fmaxf(l0, l1);
    if (j < 8) m = fmaxf(m, l2);
    #pragma unroll
    for (int off = 8; off > 0; off >>= 1)
        m = fmaxf(m, __shfl_xor_sync(0xffffffffu, m, off));
    float ssum = __expf(l0 - m) + __expf(l1 - m) + ((j < 8) ? __expf(l2 - m) : 0.f);
    #pragma unroll
    for (int off = 8; off > 0; off >>= 1)
        ssum += __shfl_xor_sync(0xffffffffu, ssum, off);
    float lse = m + __logf(ssum);

    out[v * 40 + j]      = l0 - lse;
    out[v * 40 + j + 16] = l1 - lse;
    if (j < 8) out[v * 40 + j + 32] = l2 - lse;
}

// ---------------- launch (k_xw1 at slot 4 for ncu visibility) --------------
extern "C" void kernel_launch(void* const* d_in, const int* in_sizes, int n_in,
                              void* d_out, int out_size) {
    const float* x     = (const float*)d_in[0];
    const void*  edges = d_in[1];
    const float* W1    = (const float*)d_in[2];
    const float* b1    = (const float*)d_in[3];
    const float* W2    = (const float*)d_in[4];
    const float* b2    = (const float*)d_in[5];
    const float* wihF  = (const float*)d_in[6];
    const float* whhF  = (const float*)d_in[7];
    const float* bF    = (const float*)d_in[8];
    const float* wihB  = (const float*)d_in[9];
    const float* whhB  = (const float*)d_in[10];
    const float* bB    = (const float*)d_in[11];
    const float* attw  = (const float*)d_in[12];
    const float* linw  = (const float*)d_in[14];
    const float* linb  = (const float*)d_in[15];
    float* out = (float*)d_out;

    k_init<<<(NN + 255) / 256, 256>>>((const unsigned*)edges);
    k_deg<<<NE / 256, 256>>>(edges);
    k_part<<<196, 512>>>();
    k_xw1<<<(NN / 2 + 127) / 128, 128>>>(x, W1);   // slot 4 -> ncu captures this
    k_scanpart<<<1, 256>>>();
    k_rowptr<<<196, 512>>>();
    k_scatter<<<NE / 256, 256>>>(edges);
    k_agg1<<<NN / 16, 256>>>(b1, W2);
    k_agg2<<<NN / 16, 256>>>(b2);
    k_lstm<<<(NN + 255) / 256, 256>>>(wihF, whhF, bF, wihB, whhB, bB, attw);
    k_out<<<NN / 16, 256>>>(linw, linb, out);
}